// round 1
// baseline (speedup 1.0000x reference)
#include <cuda_runtime.h>

#define Bn 4
#define Sn 256
#define Hn 160
#define NHn 8
#define HDn 20
#define FFn 640
#define MAXLENn 512
#define TBLn 1025
#define BSn (Bn*Sn)
#define R2 8

// ------------------------- device scratch (static, no allocs) ----------------
__device__ float dP[4 * TBLn * Hn];        // fused pe tables @ W_fus blocks (+b_fus in table 0)
__device__ float dWrT[Hn * Hn];            // Wr transposed
__device__ float dK[BSn * Hn];
__device__ float dV[BSn * Hn];
__device__ float dQU[BSn * Hn];            // q + u
__device__ float dG[BSn * NHn * Hn];       // g[b,i,h,c]
__device__ float dAC[Bn * NHn * Sn * Sn];  // A_C scores
__device__ float dATT[BSn * Hn];           // attention output (pre W_fin)
__device__ float dY1[BSn * Hn];            // after fin-proj + LN1
__device__ float dH1[BSn * FFn];           // FFN hidden

// ------------------------- K1: P_t = pe_t @ W_fus[t] (+ b_fus for t=0) -------
__global__ void k_tables(const float* __restrict__ pe_ss, const float* __restrict__ pe_se,
                         const float* __restrict__ pe_es, const float* __restrict__ pe_ee,
                         const float* __restrict__ W_fus, const float* __restrict__ b_fus) {
    int t = blockIdx.x / TBLn;
    int r = blockIdx.x % TBLn;
    const float* pe = (t == 0) ? pe_ss : (t == 1) ? pe_se : (t == 2) ? pe_es : pe_ee;
    __shared__ float row[Hn];
    int c = threadIdx.x;
    row[c] = pe[r * Hn + c];
    __syncthreads();
    float acc = (t == 0) ? b_fus[c] : 0.f;
    const float* wf = W_fus + t * Hn * Hn;
#pragma unroll 4
    for (int k = 0; k < Hn; k++) acc += row[k] * wf[k * Hn + c];
    dP[(t * TBLn + r) * Hn + c] = acc;
}

// ------------------------- K1b: transpose Wr --------------------------------
__global__ void k_transpose(const float* __restrict__ Wr) {
    int hd = blockIdx.x;
    int c = threadIdx.x;
    dWrT[hd * Hn + c] = Wr[c * Hn + hd];
}

// ------------------------- K2: q/k/v projections + g ------------------------
__global__ void k_qkvg(const float* __restrict__ inp,
                       const float* __restrict__ Wq, const float* __restrict__ bq,
                       const float* __restrict__ Wk, const float* __restrict__ bk,
                       const float* __restrict__ Wv, const float* __restrict__ bv,
                       const float* __restrict__ u, const float* __restrict__ v) {
    int row0 = blockIdx.x * R2;   // global row index b*S+i
    int c = threadIdx.x;          // 0..159
    __shared__ float xs[R2][Hn];
    __shared__ float qv[R2][Hn];
#pragma unroll
    for (int r = 0; r < R2; r++) xs[r][c] = inp[(row0 + r) * Hn + c];
    __syncthreads();

    float acc[R2];
    // Q
#pragma unroll
    for (int r = 0; r < R2; r++) acc[r] = bq[c];
    for (int k = 0; k < Hn; k++) {
        float w = Wq[k * Hn + c];
#pragma unroll
        for (int r = 0; r < R2; r++) acc[r] += xs[r][k] * w;
    }
    {
        float uu = u[c], vv = v[c];  // u,v are [8,20] contiguous == indexed by c
#pragma unroll
        for (int r = 0; r < R2; r++) {
            dQU[(row0 + r) * Hn + c] = acc[r] + uu;
            qv[r][c] = acc[r] + vv;
        }
    }
    // K
#pragma unroll
    for (int r = 0; r < R2; r++) acc[r] = bk[c];
    for (int k = 0; k < Hn; k++) {
        float w = Wk[k * Hn + c];
#pragma unroll
        for (int r = 0; r < R2; r++) acc[r] += xs[r][k] * w;
    }
#pragma unroll
    for (int r = 0; r < R2; r++) dK[(row0 + r) * Hn + c] = acc[r];
    // V
#pragma unroll
    for (int r = 0; r < R2; r++) acc[r] = bv[c];
    for (int k = 0; k < Hn; k++) {
        float w = Wv[k * Hn + c];
#pragma unroll
        for (int r = 0; r < R2; r++) acc[r] += xs[r][k] * w;
    }
#pragma unroll
    for (int r = 0; r < R2; r++) dV[(row0 + r) * Hn + c] = acc[r];
    __syncthreads();

    // g[b,i,h,c] = sum_d WrT[h*20+d][c] * qv[b,i,h*20+d]
    for (int h = 0; h < NHn; h++) {
        float a2[R2];
#pragma unroll
        for (int r = 0; r < R2; r++) a2[r] = 0.f;
#pragma unroll
        for (int d = 0; d < HDn; d++) {
            float w = dWrT[(h * HDn + d) * Hn + c];
#pragma unroll
            for (int r = 0; r < R2; r++) a2[r] += qv[r][h * HDn + d] * w;
        }
#pragma unroll
        for (int r = 0; r < R2; r++) dG[((row0 + r) * NHn + h) * Hn + c] = a2[r];
    }
}

// ------------------------- K2b: A_C = (q+u) @ k^T per (b,h) -----------------
__global__ void k_ac() {
    int bh = blockIdx.x;
    int b = bh / NHn, h = bh % NHn;
    __shared__ float qs[Sn * HDn];
    __shared__ float ks[Sn * HDn];
    for (int t = threadIdx.x; t < Sn * HDn; t += blockDim.x) {
        int i = t / HDn, d = t % HDn;
        qs[t] = dQU[(b * Sn + i) * Hn + h * HDn + d];
        ks[t] = dK[(b * Sn + i) * Hn + h * HDn + d];
    }
    __syncthreads();
    int j = threadIdx.x;
    float kr[HDn];
#pragma unroll
    for (int d = 0; d < HDn; d++) kr[d] = ks[j * HDn + d];
    float* out = dAC + (size_t)(b * NHn + h) * Sn * Sn + j;
#pragma unroll 2
    for (int i = 0; i < Sn; i++) {
        float a = 0.f;
#pragma unroll
        for (int d = 0; d < HDn; d++) a += qs[i * HDn + d] * kr[d];
        out[i * Sn] = a;
    }
}

// ------------------------- K3: fused rel-gather + B_D + softmax + attn@V ----
__global__ void __launch_bounds__(256) k_attn(const int* __restrict__ pos_s,
                                              const int* __restrict__ pos_e,
                                              const int* __restrict__ seq_len,
                                              const int* __restrict__ lex) {
    int b = blockIdx.x >> 8;
    int i = blockIdx.x & 255;
    int tid = threadIdx.x;
    int lane = tid & 31;
    int w = tid >> 5;

    __shared__ float sc[NHn][Sn];
    __shared__ int pss[Sn], pes[Sn];
    __shared__ float rinv[NHn];

    pss[tid] = pos_s[b * Sn + tid];
    pes[tid] = pos_e[b * Sn + tid];

    // g for this (b,i) into registers: g[h][cc] covers channel c = lane + 32*cc
    float g[NHn][5];
    {
        const float* gp = dG + (size_t)(b * Sn + i) * NHn * Hn;
#pragma unroll
        for (int h = 0; h < NHn; h++)
#pragma unroll
            for (int cc = 0; cc < 5; cc++) g[h][cc] = gp[h * Hn + lane + cc * 32];
    }
    __syncthreads();

    int psi = pss[i], pei = pes[i];
    const float* b0 = dP + (size_t)(0 * TBLn + psi + MAXLENn) * Hn;
    const float* b1 = dP + (size_t)(1 * TBLn + psi + MAXLENn) * Hn;
    const float* b2 = dP + (size_t)(2 * TBLn + pei + MAXLENn) * Hn;
    const float* b3 = dP + (size_t)(3 * TBLn + pei + MAXLENn) * Hn;

#pragma unroll 1
    for (int jj = 0; jj < 32; jj++) {
        int j = w * 32 + jj;
        int os = pss[j] * Hn;
        int oe = pes[j] * Hn;
        const float* r0 = b0 - os;
        const float* r1 = b1 - oe;
        const float* r2 = b2 - os;
        const float* r3 = b3 - oe;
        float acc[NHn];
#pragma unroll
        for (int h = 0; h < NHn; h++) acc[h] = 0.f;
#pragma unroll
        for (int cc = 0; cc < 5; cc++) {
            int c = lane + cc * 32;
            float rel = r0[c] + r1[c] + r2[c] + r3[c];
            rel = fmaxf(rel, 0.f);
#pragma unroll
            for (int h = 0; h < NHn; h++) acc[h] += rel * g[h][cc];
        }
#pragma unroll
        for (int off = 16; off; off >>= 1)
#pragma unroll
            for (int h = 0; h < NHn; h++) acc[h] += __shfl_xor_sync(0xffffffffu, acc[h], off);
        if (lane == 0) {
#pragma unroll
            for (int h = 0; h < NHn; h++) sc[h][j] = acc[h];
        }
    }
    __syncthreads();

    // add A_C, scale, mask
    {
        int j = tid;
        int lim = seq_len[b] + lex[0];
        bool valid = j < lim;
        const float scale = 0.223606797749979f;  // 1/sqrt(20)
        const float* ac = dAC + ((size_t)(b * NHn) * Sn + i) * Sn + j;
#pragma unroll
        for (int h = 0; h < NHn; h++) {
            float s = (sc[h][j] + ac[(size_t)h * Sn * Sn]) * scale;
            sc[h][j] = valid ? s : -1e15f;
        }
    }
    __syncthreads();

    // per-head softmax (warp w handles head w); leave p unnormalized, keep 1/sum
    {
        int h = w;
        float m = -1e30f;
#pragma unroll
        for (int q = 0; q < 8; q++) m = fmaxf(m, sc[h][lane + q * 32]);
#pragma unroll
        for (int off = 16; off; off >>= 1) m = fmaxf(m, __shfl_xor_sync(0xffffffffu, m, off));
        float ssum = 0.f;
#pragma unroll
        for (int q = 0; q < 8; q++) {
            float p = __expf(sc[h][lane + q * 32] - m);
            sc[h][lane + q * 32] = p;
            ssum += p;
        }
#pragma unroll
        for (int off = 16; off; off >>= 1) ssum += __shfl_xor_sync(0xffffffffu, ssum, off);
        if (lane == 0) rinv[h] = 1.0f / ssum;
    }
    __syncthreads();

    // out[c] = (sum_j p[h][j] * V[b,j,c]) * rinv[h]
    if (tid < Hn) {
        int c = tid;
        int h = c / HDn;
        const float* vp = dV + (size_t)b * Sn * Hn + c;
        float acc = 0.f;
#pragma unroll 4
        for (int j = 0; j < Sn; j++) acc += sc[h][j] * vp[(size_t)j * Hn];
        dATT[((size_t)b * Sn + i) * Hn + c] = acc * rinv[h];
    }
}

// ------------------------- LN helper pattern used in K4/K6 ------------------
// (inlined in each kernel; blockDim must be 160 = 5 warps)

// ------------------------- K4: @W_fin + b_fin, x2, LN1 ----------------------
__global__ void k_fin_ln(const float* __restrict__ W_fin, const float* __restrict__ b_fin,
                         const float* __restrict__ g1, const float* __restrict__ be1) {
    int row0 = blockIdx.x * R2;
    int c = threadIdx.x;
    int lane = c & 31, w = c >> 5;
    __shared__ float xs[R2][Hn];
    __shared__ float ys[R2][Hn];
    __shared__ float part1[5], part2[5];
    __shared__ float mu_s, rs_s;
#pragma unroll
    for (int r = 0; r < R2; r++) xs[r][c] = dATT[(row0 + r) * Hn + c];
    __syncthreads();
    float acc[R2];
#pragma unroll
    for (int r = 0; r < R2; r++) acc[r] = b_fin[c];
    for (int k = 0; k < Hn; k++) {
        float ww = W_fin[k * Hn + c];
#pragma unroll
        for (int r = 0; r < R2; r++) acc[r] += xs[r][k] * ww;
    }
#pragma unroll
    for (int r = 0; r < R2; r++) ys[r][c] = 2.f * acc[r];
    __syncthreads();
    for (int r = 0; r < R2; r++) {
        float v = ys[r][c];
        float s1 = v, s2 = v * v;
#pragma unroll
        for (int off = 16; off; off >>= 1) {
            s1 += __shfl_xor_sync(0xffffffffu, s1, off);
            s2 += __shfl_xor_sync(0xffffffffu, s2, off);
        }
        if (lane == 0) { part1[w] = s1; part2[w] = s2; }
        __syncthreads();
        if (c == 0) {
            float a = 0.f, q = 0.f;
#pragma unroll
            for (int t = 0; t < 5; t++) { a += part1[t]; q += part2[t]; }
            float mu = a / Hn;
            mu_s = mu;
            rs_s = rsqrtf(q / Hn - mu * mu + 1e-5f);
        }
        __syncthreads();
        dY1[(row0 + r) * Hn + c] = (v - mu_s) * rs_s * g1[c] + be1[c];
        __syncthreads();
    }
}

// ------------------------- K5: FFN1 = relu(y1 @ W1 + b1) --------------------
__global__ void k_ffn1(const float* __restrict__ W1, const float* __restrict__ b1) {
    int row0 = blockIdx.x * R2;
    int t = threadIdx.x;  // 320 threads
    __shared__ float xs[R2 * Hn];
    for (int q = t; q < R2 * Hn; q += 320) xs[q] = dY1[row0 * Hn + q];
    __syncthreads();
    int c0 = t, c1 = t + 320;
    float a0[R2], a1[R2];
#pragma unroll
    for (int r = 0; r < R2; r++) { a0[r] = b1[c0]; a1[r] = b1[c1]; }
    for (int k = 0; k < Hn; k++) {
        float w0 = W1[k * FFn + c0];
        float w1 = W1[k * FFn + c1];
#pragma unroll
        for (int r = 0; r < R2; r++) {
            float x = xs[r * Hn + k];
            a0[r] += x * w0;
            a1[r] += x * w1;
        }
    }
#pragma unroll
    for (int r = 0; r < R2; r++) {
        dH1[(row0 + r) * FFn + c0] = fmaxf(a0[r], 0.f);
        dH1[(row0 + r) * FFn + c1] = fmaxf(a1[r], 0.f);
    }
}

// ------------------------- K6: FFN2 + b2, x2, LN2 -> out --------------------
__global__ void k_ffn2_ln(const float* __restrict__ W2, const float* __restrict__ b2,
                          const float* __restrict__ g2, const float* __restrict__ be2,
                          float* __restrict__ out) {
    int row0 = blockIdx.x * R2;
    int c = threadIdx.x;  // 160
    int lane = c & 31, w = c >> 5;
    __shared__ float hs[R2 * FFn];
    __shared__ float ys[R2][Hn];
    __shared__ float part1[5], part2[5];
    __shared__ float mu_s, rs_s;
    for (int q = c; q < R2 * FFn; q += Hn) hs[q] = dH1[row0 * FFn + q];
    __syncthreads();
    float acc[R2];
#pragma unroll
    for (int r = 0; r < R2; r++) acc[r] = b2[c];
    for (int k = 0; k < FFn; k++) {
        float ww = W2[k * Hn + c];
#pragma unroll
        for (int r = 0; r < R2; r++) acc[r] += hs[r * FFn + k] * ww;
    }
#pragma unroll
    for (int r = 0; r < R2; r++) ys[r][c] = 2.f * acc[r];
    __syncthreads();
    for (int r = 0; r < R2; r++) {
        float v = ys[r][c];
        float s1 = v, s2 = v * v;
#pragma unroll
        for (int off = 16; off; off >>= 1) {
            s1 += __shfl_xor_sync(0xffffffffu, s1, off);
            s2 += __shfl_xor_sync(0xffffffffu, s2, off);
        }
        if (lane == 0) { part1[w] = s1; part2[w] = s2; }
        __syncthreads();
        if (c == 0) {
            float a = 0.f, q = 0.f;
#pragma unroll
            for (int t = 0; t < 5; t++) { a += part1[t]; q += part2[t]; }
            float mu = a / Hn;
            mu_s = mu;
            rs_s = rsqrtf(q / Hn - mu * mu + 1e-5f);
        }
        __syncthreads();
        out[(row0 + r) * Hn + c] = (v - mu_s) * rs_s * g2[c] + be2[c];
        __syncthreads();
    }
}

// ------------------------- launch -------------------------------------------
extern "C" void kernel_launch(void* const* d_in, const int* in_sizes, int n_in,
                              void* d_out, int out_size) {
    const float* inp   = (const float*)d_in[0];
    const int* pos_s   = (const int*)d_in[1];
    const int* pos_e   = (const int*)d_in[2];
    const int* seq_len = (const int*)d_in[3];
    const int* lex     = (const int*)d_in[4];
    const float* pe_ss = (const float*)d_in[5];
    const float* pe_se = (const float*)d_in[6];
    const float* pe_es = (const float*)d_in[7];
    const float* pe_ee = (const float*)d_in[8];
    const float* W_fus = (const float*)d_in[9];
    const float* b_fus = (const float*)d_in[10];
    const float* Wq    = (const float*)d_in[11];
    const float* bq    = (const float*)d_in[12];
    const float* Wk    = (const float*)d_in[13];
    const float* bk    = (const float*)d_in[14];
    const float* Wv    = (const float*)d_in[15];
    const float* bv    = (const float*)d_in[16];
    const float* Wr    = (const float*)d_in[17];
    // d_in[18] = br: constant over j inside softmax -> cancels exactly, unused
    const float* u     = (const float*)d_in[19];
    const float* v     = (const float*)d_in[20];
    const float* W_fin = (const float*)d_in[21];
    const float* b_fin = (const float*)d_in[22];
    const float* ln1_g = (const float*)d_in[23];
    const float* ln1_b = (const float*)d_in[24];
    const float* W1    = (const float*)d_in[25];
    const float* b1    = (const float*)d_in[26];
    const float* W2    = (const float*)d_in[27];
    const float* b2    = (const float*)d_in[28];
    const float* ln2_g = (const float*)d_in[29];
    const float* ln2_b = (const float*)d_in[30];

    k_tables<<<4 * TBLn, Hn>>>(pe_ss, pe_se, pe_es, pe_ee, W_fus, b_fus);
    k_transpose<<<Hn, Hn>>>(Wr);
    k_qkvg<<<BSn / R2, Hn>>>(inp, Wq, bq, Wk, bk, Wv, bv, u, v);
    k_ac<<<Bn * NHn, Sn>>>();
    k_attn<<<BSn, 256>>>(pos_s, pos_e, seq_len, lex);
    k_fin_ln<<<BSn / R2, Hn>>>(W_fin, b_fin, ln1_g, ln1_b);
    k_ffn1<<<BSn / R2, 320>>>(W1, b1);
    k_ffn2_ln<<<BSn / R2, Hn>>>(W2, b2, ln2_g, ln2_b, (float*)d_out);
}

// round 2
// speedup vs baseline: 1.0446x; 1.0446x over previous
#include <cuda_runtime.h>
#include <cuda_fp16.h>

#define Bn 4
#define Sn 256
#define Hn 160
#define NHn 8
#define HDn 20
#define FFn 640
#define MAXLENn 512
#define TBLn 1025
#define BSn (Bn*Sn)
#define R2 8
#define TR 8
#define TBLOCKS 129   // ceil(1025/8)

// ------------------------- device scratch (static, no allocs) ----------------
__device__ uint2 dPh4[4 * TBLn * (Hn / 4)];  // fused pe tables in fp16 (rows of 40 uint2 = 160 half)
__device__ float dWrT[Hn * Hn];              // Wr transposed
__device__ float dK[BSn * Hn];
__device__ float dV[BSn * Hn];
__device__ float dQU[BSn * Hn];              // q + u
__device__ float dG[BSn * NHn * Hn];         // g[b,i,h,c]
__device__ float dAC[Bn * NHn * Sn * Sn];    // A_C scores
__device__ float dATT[BSn * Hn];             // attention output (pre W_fin)
__device__ float dY1[BSn * Hn];              // after fin-proj + LN1
__device__ float dH1[BSn * FFn];             // FFN hidden

// ------------------------- K1: P_t = pe_t @ W_fus[t] (+ b_fus for t=0), fp16 out
__global__ void k_tables(const float* __restrict__ pe_ss, const float* __restrict__ pe_se,
                         const float* __restrict__ pe_es, const float* __restrict__ pe_ee,
                         const float* __restrict__ W_fus, const float* __restrict__ b_fus) {
    int t = blockIdx.x / TBLOCKS;
    int r0 = (blockIdx.x % TBLOCKS) * TR;
    const float* pe = (t == 0) ? pe_ss : (t == 1) ? pe_se : (t == 2) ? pe_es : pe_ee;
    __shared__ float rows[TR][Hn];
    int c = threadIdx.x;
#pragma unroll
    for (int r = 0; r < TR; r++) {
        int rr = r0 + r;
        rows[r][c] = (rr < TBLn) ? pe[rr * Hn + c] : 0.f;
    }
    __syncthreads();
    float bias = (t == 0) ? b_fus[c] : 0.f;
    float acc[TR];
#pragma unroll
    for (int r = 0; r < TR; r++) acc[r] = bias;
    const float* wf = W_fus + t * Hn * Hn;
    for (int k = 0; k < Hn; k++) {
        float w = wf[k * Hn + c];
#pragma unroll
        for (int r = 0; r < TR; r++) acc[r] += rows[r][k] * w;
    }
    __half* out = (__half*)dPh4;
#pragma unroll
    for (int r = 0; r < TR; r++) {
        int rr = r0 + r;
        if (rr < TBLn) out[(size_t)(t * TBLn + rr) * Hn + c] = __float2half(acc[r]);
    }
}

// ------------------------- K1b: transpose Wr --------------------------------
__global__ void k_transpose(const float* __restrict__ Wr) {
    int hd = blockIdx.x;
    int c = threadIdx.x;
    dWrT[hd * Hn + c] = Wr[c * Hn + hd];
}

// ------------------------- K2: q/k/v projections + g ------------------------
__global__ void k_qkvg(const float* __restrict__ inp,
                       const float* __restrict__ Wq, const float* __restrict__ bq,
                       const float* __restrict__ Wk, const float* __restrict__ bk,
                       const float* __restrict__ Wv, const float* __restrict__ bv,
                       const float* __restrict__ u, const float* __restrict__ v) {
    int row0 = blockIdx.x * R2;
    int c = threadIdx.x;
    __shared__ float xs[R2][Hn];
    __shared__ float qv[R2][Hn];
#pragma unroll
    for (int r = 0; r < R2; r++) xs[r][c] = inp[(row0 + r) * Hn + c];
    __syncthreads();

    float acc[R2];
#pragma unroll
    for (int r = 0; r < R2; r++) acc[r] = bq[c];
    for (int k = 0; k < Hn; k++) {
        float w = Wq[k * Hn + c];
#pragma unroll
        for (int r = 0; r < R2; r++) acc[r] += xs[r][k] * w;
    }
    {
        float uu = u[c], vv = v[c];
#pragma unroll
        for (int r = 0; r < R2; r++) {
            dQU[(row0 + r) * Hn + c] = acc[r] + uu;
            qv[r][c] = acc[r] + vv;
        }
    }
#pragma unroll
    for (int r = 0; r < R2; r++) acc[r] = bk[c];
    for (int k = 0; k < Hn; k++) {
        float w = Wk[k * Hn + c];
#pragma unroll
        for (int r = 0; r < R2; r++) acc[r] += xs[r][k] * w;
    }
#pragma unroll
    for (int r = 0; r < R2; r++) dK[(row0 + r) * Hn + c] = acc[r];
#pragma unroll
    for (int r = 0; r < R2; r++) acc[r] = bv[c];
    for (int k = 0; k < Hn; k++) {
        float w = Wv[k * Hn + c];
#pragma unroll
        for (int r = 0; r < R2; r++) acc[r] += xs[r][k] * w;
    }
#pragma unroll
    for (int r = 0; r < R2; r++) dV[(row0 + r) * Hn + c] = acc[r];
    __syncthreads();

    for (int h = 0; h < NHn; h++) {
        float a2[R2];
#pragma unroll
        for (int r = 0; r < R2; r++) a2[r] = 0.f;
#pragma unroll
        for (int d = 0; d < HDn; d++) {
            float w = dWrT[(h * HDn + d) * Hn + c];
#pragma unroll
            for (int r = 0; r < R2; r++) a2[r] += qv[r][h * HDn + d] * w;
        }
#pragma unroll
        for (int r = 0; r < R2; r++) dG[((row0 + r) * NHn + h) * Hn + c] = a2[r];
    }
}

// ------------------------- K2b: A_C = (q+u) @ k^T, one (b,h,ichunk) per block
__global__ void __launch_bounds__(256) k_ac() {
    int blk = blockIdx.x;            // b*32 + h*4 + ic
    int b = blk >> 5;
    int h = (blk >> 2) & 7;
    int ic = blk & 3;
    __shared__ float qs[64 * HDn];
    __shared__ float ks[Sn * HDn];
    int tid = threadIdx.x;           // 256 = j
    {
        const float* kp = dK + (size_t)(b * Sn + tid) * Hn + h * HDn;
#pragma unroll
        for (int d = 0; d < HDn; d++) ks[tid * HDn + d] = kp[d];
    }
    if (tid < 64) {
        const float* qp = dQU + (size_t)(b * Sn + ic * 64 + tid) * Hn + h * HDn;
#pragma unroll
        for (int d = 0; d < HDn; d++) qs[tid * HDn + d] = qp[d];
    }
    __syncthreads();
    float kr[HDn];
#pragma unroll
    for (int d = 0; d < HDn; d++) kr[d] = ks[tid * HDn + d];
    float* out = dAC + (size_t)(b * NHn + h) * Sn * Sn + (size_t)(ic * 64) * Sn + tid;
#pragma unroll 4
    for (int ii = 0; ii < 64; ii++) {
        float a = 0.f;
#pragma unroll
        for (int d = 0; d < HDn; d++) a += qs[ii * HDn + d] * kr[d];
        out[(size_t)ii * Sn] = a;
    }
}

// ------------------------- K3: fused rel-gather + B_D + softmax + attn@V ----
__device__ __forceinline__ float2 h2sumf(unsigned a, unsigned b) {
    __half2 ha = *reinterpret_cast<const __half2*>(&a);
    __half2 hb = *reinterpret_cast<const __half2*>(&b);
    return __half22float2(__hadd2(ha, hb));
}

__global__ void __launch_bounds__(256) k_attn(const int* __restrict__ pos_s,
                                              const int* __restrict__ pos_e,
                                              const int* __restrict__ seq_len,
                                              const int* __restrict__ lex) {
    int b = blockIdx.x >> 8;
    int i = blockIdx.x & 255;
    int tid = threadIdx.x;
    int lane = tid & 31;
    int w = tid >> 5;
    int l8 = lane & 7;
    int q8 = lane >> 3;

    __shared__ float sc[NHn][Sn];
    __shared__ int pss[Sn], pes[Sn];
    __shared__ __align__(16) float g_s[NHn * Hn];
    __shared__ float rinv[NHn];

    pss[tid] = pos_s[b * Sn + tid];
    pes[tid] = pos_e[b * Sn + tid];
    {
        const float* gp = dG + (size_t)(b * Sn + i) * NHn * Hn;
#pragma unroll
        for (int t = tid; t < NHn * Hn; t += 256) g_s[t] = gp[t];
    }
    __syncthreads();

    int psi = pss[i] + MAXLENn;
    int pei = pes[i] + MAXLENn;

#pragma unroll 1
    for (int s = 0; s < 8; s++) {
        int j = (w << 5) + (s << 2) + q8;
        int osj = pss[j], oej = pes[j];
        const uint2* p0 = dPh4 + (size_t)(0 * TBLn + psi - osj) * 40 + l8;
        const uint2* p1 = dPh4 + (size_t)(1 * TBLn + psi - oej) * 40 + l8;
        const uint2* p2 = dPh4 + (size_t)(2 * TBLn + pei - osj) * 40 + l8;
        const uint2* p3 = dPh4 + (size_t)(3 * TBLn + pei - oej) * 40 + l8;

        float rel[20];
#pragma unroll
        for (int cc = 0; cc < 5; cc++) {
            uint2 a0 = p0[cc * 8];
            uint2 a1 = p1[cc * 8];
            uint2 a2 = p2[cc * 8];
            uint2 a3 = p3[cc * 8];
            float2 sx = h2sumf(a0.x, a1.x);
            float2 tx = h2sumf(a2.x, a3.x);
            rel[cc * 4 + 0] = fmaxf(sx.x + tx.x, 0.f);
            rel[cc * 4 + 1] = fmaxf(sx.y + tx.y, 0.f);
            float2 sy = h2sumf(a0.y, a1.y);
            float2 ty = h2sumf(a2.y, a3.y);
            rel[cc * 4 + 2] = fmaxf(sy.x + ty.x, 0.f);
            rel[cc * 4 + 3] = fmaxf(sy.y + ty.y, 0.f);
        }

        float acc[NHn];
#pragma unroll
        for (int h = 0; h < NHn; h++) acc[h] = 0.f;
#pragma unroll
        for (int h = 0; h < NHn; h++) {
            const float4* g4 = reinterpret_cast<const float4*>(g_s + h * Hn);
#pragma unroll
            for (int cc = 0; cc < 5; cc++) {
                float4 gg = g4[l8 + cc * 8];
                acc[h] += rel[cc * 4 + 0] * gg.x + rel[cc * 4 + 1] * gg.y +
                          rel[cc * 4 + 2] * gg.z + rel[cc * 4 + 3] * gg.w;
            }
        }
#pragma unroll
        for (int off = 4; off; off >>= 1)
#pragma unroll
            for (int h = 0; h < NHn; h++) acc[h] += __shfl_xor_sync(0xffffffffu, acc[h], off);
#pragma unroll
        for (int h = 0; h < NHn; h++)
            if (l8 == h) sc[h][j] = acc[h];
    }
    __syncthreads();

    // add A_C, scale, mask
    {
        int j = tid;
        int lim = seq_len[b] + lex[0];
        bool valid = j < lim;
        const float scale = 0.223606797749979f;
        const float* ac = dAC + ((size_t)(b * NHn) * Sn + i) * Sn + j;
#pragma unroll
        for (int h = 0; h < NHn; h++) {
            float s = (sc[h][j] + ac[(size_t)h * Sn * Sn]) * scale;
            sc[h][j] = valid ? s : -1e15f;
        }
    }
    __syncthreads();

    // per-head softmax (warp w handles head w); unnormalized p + 1/sum
    {
        int h = w;
        float m = -1e30f;
#pragma unroll
        for (int q = 0; q < 8; q++) m = fmaxf(m, sc[h][lane + q * 32]);
#pragma unroll
        for (int off = 16; off; off >>= 1) m = fmaxf(m, __shfl_xor_sync(0xffffffffu, m, off));
        float ssum = 0.f;
#pragma unroll
        for (int q = 0; q < 8; q++) {
            float p = __expf(sc[h][lane + q * 32] - m);
            sc[h][lane + q * 32] = p;
            ssum += p;
        }
#pragma unroll
        for (int off = 16; off; off >>= 1) ssum += __shfl_xor_sync(0xffffffffu, ssum, off);
        if (lane == 0) rinv[h] = 1.0f / ssum;
    }
    __syncthreads();

    // out[c] = (sum_j p[h][j] * V[b,j,c]) * rinv[h]
    if (tid < Hn) {
        int c = tid;
        int h = c / HDn;
        const float* vp = dV + (size_t)b * Sn * Hn + c;
        float acc = 0.f;
#pragma unroll 8
        for (int j = 0; j < Sn; j++) acc += sc[h][j] * vp[(size_t)j * Hn];
        dATT[((size_t)b * Sn + i) * Hn + c] = acc * rinv[h];
    }
}

// ------------------------- K4: @W_fin + b_fin, x2, LN1 ----------------------
__global__ void k_fin_ln(const float* __restrict__ W_fin, const float* __restrict__ b_fin,
                         const float* __restrict__ g1, const float* __restrict__ be1) {
    int row0 = blockIdx.x * R2;
    int c = threadIdx.x;
    int lane = c & 31, w = c >> 5;
    __shared__ float xs[R2][Hn];
    __shared__ float ys[R2][Hn];
    __shared__ float part1[5], part2[5];
    __shared__ float mu_s, rs_s;
#pragma unroll
    for (int r = 0; r < R2; r++) xs[r][c] = dATT[(row0 + r) * Hn + c];
    __syncthreads();
    float acc[R2];
#pragma unroll
    for (int r = 0; r < R2; r++) acc[r] = b_fin[c];
    for (int k = 0; k < Hn; k++) {
        float ww = W_fin[k * Hn + c];
#pragma unroll
        for (int r = 0; r < R2; r++) acc[r] += xs[r][k] * ww;
    }
#pragma unroll
    for (int r = 0; r < R2; r++) ys[r][c] = 2.f * acc[r];
    __syncthreads();
    for (int r = 0; r < R2; r++) {
        float v = ys[r][c];
        float s1 = v, s2 = v * v;
#pragma unroll
        for (int off = 16; off; off >>= 1) {
            s1 += __shfl_xor_sync(0xffffffffu, s1, off);
            s2 += __shfl_xor_sync(0xffffffffu, s2, off);
        }
        if (lane == 0) { part1[w] = s1; part2[w] = s2; }
        __syncthreads();
        if (c == 0) {
            float a = 0.f, q = 0.f;
#pragma unroll
            for (int t = 0; t < 5; t++) { a += part1[t]; q += part2[t]; }
            float mu = a / Hn;
            mu_s = mu;
            rs_s = rsqrtf(q / Hn - mu * mu + 1e-5f);
        }
        __syncthreads();
        dY1[(row0 + r) * Hn + c] = (v - mu_s) * rs_s * g1[c] + be1[c];
        __syncthreads();
    }
}

// ------------------------- K5: FFN1 = relu(y1 @ W1 + b1) --------------------
__global__ void k_ffn1(const float* __restrict__ W1, const float* __restrict__ b1) {
    int row0 = blockIdx.x * R2;
    int t = threadIdx.x;  // 320 threads
    __shared__ float xs[R2 * Hn];
    for (int q = t; q < R2 * Hn; q += 320) xs[q] = dY1[row0 * Hn + q];
    __syncthreads();
    int c0 = t, c1 = t + 320;
    float a0[R2], a1[R2];
#pragma unroll
    for (int r = 0; r < R2; r++) { a0[r] = b1[c0]; a1[r] = b1[c1]; }
    for (int k = 0; k < Hn; k++) {
        float w0 = W1[k * FFn + c0];
        float w1 = W1[k * FFn + c1];
#pragma unroll
        for (int r = 0; r < R2; r++) {
            float x = xs[r * Hn + k];
            a0[r] += x * w0;
            a1[r] += x * w1;
        }
    }
#pragma unroll
    for (int r = 0; r < R2; r++) {
        dH1[(row0 + r) * FFn + c0] = fmaxf(a0[r], 0.f);
        dH1[(row0 + r) * FFn + c1] = fmaxf(a1[r], 0.f);
    }
}

// ------------------------- K6: FFN2 + b2, x2, LN2 -> out --------------------
__global__ void k_ffn2_ln(const float* __restrict__ W2, const float* __restrict__ b2,
                          const float* __restrict__ g2, const float* __restrict__ be2,
                          float* __restrict__ out) {
    int row0 = blockIdx.x * R2;
    int c = threadIdx.x;  // 160
    int lane = c & 31, w = c >> 5;
    __shared__ float hs[R2 * FFn];
    __shared__ float ys[R2][Hn];
    __shared__ float part1[5], part2[5];
    __shared__ float mu_s, rs_s;
    for (int q = c; q < R2 * FFn; q += Hn) hs[q] = dH1[row0 * FFn + q];
    __syncthreads();
    float acc[R2];
#pragma unroll
    for (int r = 0; r < R2; r++) acc[r] = b2[c];
    for (int k = 0; k < FFn; k++) {
        float ww = W2[k * Hn + c];
#pragma unroll
        for (int r = 0; r < R2; r++) acc[r] += hs[r * FFn + k] * ww;
    }
#pragma unroll
    for (int r = 0; r < R2; r++) ys[r][c] = 2.f * acc[r];
    __syncthreads();
    for (int r = 0; r < R2; r++) {
        float v = ys[r][c];
        float s1 = v, s2 = v * v;
#pragma unroll
        for (int off = 16; off; off >>= 1) {
            s1 += __shfl_xor_sync(0xffffffffu, s1, off);
            s2 += __shfl_xor_sync(0xffffffffu, s2, off);
        }
        if (lane == 0) { part1[w] = s1; part2[w] = s2; }
        __syncthreads();
        if (c == 0) {
            float a = 0.f, q = 0.f;
#pragma unroll
            for (int t = 0; t < 5; t++) { a += part1[t]; q += part2[t]; }
            float mu = a / Hn;
            mu_s = mu;
            rs_s = rsqrtf(q / Hn - mu * mu + 1e-5f);
        }
        __syncthreads();
        out[(row0 + r) * Hn + c] = (v - mu_s) * rs_s * g2[c] + be2[c];
        __syncthreads();
    }
}

// ------------------------- launch -------------------------------------------
extern "C" void kernel_launch(void* const* d_in, const int* in_sizes, int n_in,
                              void* d_out, int out_size) {
    const float* inp   = (const float*)d_in[0];
    const int* pos_s   = (const int*)d_in[1];
    const int* pos_e   = (const int*)d_in[2];
    const int* seq_len = (const int*)d_in[3];
    const int* lex     = (const int*)d_in[4];
    const float* pe_ss = (const float*)d_in[5];
    const float* pe_se = (const float*)d_in[6];
    const float* pe_es = (const float*)d_in[7];
    const float* pe_ee = (const float*)d_in[8];
    const float* W_fus = (const float*)d_in[9];
    const float* b_fus = (const float*)d_in[10];
    const float* Wq    = (const float*)d_in[11];
    const float* bq    = (const float*)d_in[12];
    const float* Wk    = (const float*)d_in[13];
    const float* bk    = (const float*)d_in[14];
    const float* Wv    = (const float*)d_in[15];
    const float* bv    = (const float*)d_in[16];
    const float* Wr    = (const float*)d_in[17];
    // d_in[18] = br: constant over j inside softmax -> cancels exactly, unused
    const float* u     = (const float*)d_in[19];
    const float* v     = (const float*)d_in[20];
    const float* W_fin = (const float*)d_in[21];
    const float* b_fin = (const float*)d_in[22];
    const float* ln1_g = (const float*)d_in[23];
    const float* ln1_b = (const float*)d_in[24];
    const float* W1    = (const float*)d_in[25];
    const float* b1    = (const float*)d_in[26];
    const float* W2    = (const float*)d_in[27];
    const float* b2    = (const float*)d_in[28];
    const float* ln2_g = (const float*)d_in[29];
    const float* ln2_b = (const float*)d_in[30];

    k_tables<<<4 * TBLOCKS, Hn>>>(pe_ss, pe_se, pe_es, pe_ee, W_fus, b_fus);
    k_transpose<<<Hn, Hn>>>(Wr);
    k_qkvg<<<BSn / R2, Hn>>>(inp, Wq, bq, Wk, bk, Wv, bv, u, v);
    k_ac<<<Bn * NHn * 4, 256>>>();
    k_attn<<<BSn, 256>>>(pos_s, pos_e, seq_len, lex);
    k_fin_ln<<<BSn / R2, Hn>>>(W_fin, b_fin, ln1_g, ln1_b);
    k_ffn1<<<BSn / R2, 320>>>(W1, b1);
    k_ffn2_ln<<<BSn / R2, Hn>>>(W2, b2, ln2_g, ln2_b, (float*)d_out);
}